// round 16
// baseline (speedup 1.0000x reference)
#include <cuda_runtime.h>

#define B_    256
#define C_    3
#define H_    224
#define W_    224
#define HW_   (H_ * W_)         // 50176
#define HW4   (HW_ / 4)         // 12544 float4 per plane
#define NSL   49                // slices per image
#define TOTAL (B_ * NSL)        // 12544 work items
#define NT    128
#define NCTA  888               // 148 SMs x 6 CTAs: fully co-resident

#define GW0 0.2989f
#define GW1 0.587f
#define GW2 0.114f

// Deterministic scratch. g_cnt is MONOTONIC across graph replays: epoch
// target is derived from the atomicAdd return value (no reset kernel).
__device__ float g_part[TOTAL * 3];
__device__ int   g_cnt[B_];

// ---------------------------------------------------------------------------
// Persistent depth-2 pipelined kernel. Per item (b, sl):
//   load slice (2 px/thread, 6 independent ldcs) -> post partials+arrival ->
//   non-contrast: finish now; contrast: stash in regs, finish NEXT round
//   (its image completed ~1 round ago; spin is a near-always-passed check,
//   and any residual wait overlaps the next item's loads).
// Input read exactly once: DRAM traffic = 154R + 154W = 308 MB (minimum).
// ---------------------------------------------------------------------------
__global__ __launch_bounds__(NT, 6) void fused_aug_kernel(
    const float* __restrict__ x,
    const float* __restrict__ brightness,
    const float* __restrict__ contrast_factor,
    const int*   __restrict__ flip_mask,
    const int*   __restrict__ gray_mask,
    const int*   __restrict__ contrast_apply,
    float*       __restrict__ out)
{
    const int tid = threadIdx.x;
    __shared__ float red[3][4];
    __shared__ float sm_mean[3];

    const float4* __restrict__ xin  = reinterpret_cast<const float4*>(x);
    float4*       __restrict__ oput = reinterpret_cast<float4*>(out);

    // pending (contrast) item state
    int    p_item = -1, p_b = 0, p_p0 = 0, p_tgt = 0;
    bool   p_flip = false, p_gray = false;
    float  p_br = 0.f, p_cf = 1.f;
    float4 pa0, pa1, pa2, pb0, pb1, pb2;

    #define REV(v) { float t;                                                \
        t = v.x; v.x = v.w; v.w = t;  t = v.y; v.y = v.z; v.z = t; }
    #define GRAYIFY(c0, c1, c2) {                                            \
        float4 g;                                                            \
        g.x = GW0*c0.x + GW1*c1.x + GW2*c2.x;                                \
        g.y = GW0*c0.y + GW1*c1.y + GW2*c2.y;                                \
        g.z = GW0*c0.z + GW1*c1.z + GW2*c2.z;                                \
        g.w = GW0*c0.w + GW1*c1.w + GW2*c2.w;                                \
        c0 = g; c1 = g; c2 = g; }
    #define XFORM(v, sc, off)                                                \
        v.x = fminf(fmaxf(fmaf(v.x, sc, off), -2.5f), 2.5f);                \
        v.y = fminf(fmaxf(fmaf(v.y, sc, off), -2.5f), 2.5f);                \
        v.z = fminf(fmaxf(fmaf(v.z, sc, off), -2.5f), 2.5f);                \
        v.w = fminf(fmaxf(fmaf(v.w, sc, off), -2.5f), 2.5f);

    for (int item = blockIdx.x; item < TOTAL + NCTA; item += NCTA) {
        const bool valid = item < TOTAL;

        int    b = 0, p0 = 0, tgt = 0;
        bool   flip = false, gray = false, ctr = false;
        float  br = 0.f, cf = 1.f;
        float4 a0, a1, a2, b0v, b1v, b2v;

        if (valid) {
            b = item / NSL;
            const int sl = item - b * NSL;
            p0 = sl * 256 + tid;                 // pixel A (float4 idx)
            const int p1 = p0 + 128;             // pixel B

            br   = brightness[b];
            flip = flip_mask[b] != 0;
            gray = gray_mask[b] != 0;
            ctr  = contrast_apply[b] != 0;
            cf   = ctr ? contrast_factor[b] : 1.0f;

            const int pixA = p0 * 4, hA = pixA / W_, wA = pixA - hA * W_;
            const int pixB = p1 * 4, hB = pixB / W_, wB = pixB - hB * W_;
            const int spA  = flip ? ((hA * W_ + (W_ - 4 - wA)) >> 2) : p0;
            const int spB  = flip ? ((hB * W_ + (W_ - 4 - wB)) >> 2) : p1;

            const float4* __restrict__ in4 = xin + (size_t)b * 3 * HW4;
            a0  = __ldcs(&in4[0 * HW4 + spA]);
            a1  = __ldcs(&in4[1 * HW4 + spA]);
            a2  = __ldcs(&in4[2 * HW4 + spA]);
            b0v = __ldcs(&in4[0 * HW4 + spB]);
            b1v = __ldcs(&in4[1 * HW4 + spB]);
            b2v = __ldcs(&in4[2 * HW4 + spB]);

            float s0 = (a0.x+a0.y)+(a0.z+a0.w) + (b0v.x+b0v.y)+(b0v.z+b0v.w);
            float s1 = (a1.x+a1.y)+(a1.z+a1.w) + (b1v.x+b1v.y)+(b1v.z+b1v.w);
            float s2 = (a2.x+a2.y)+(a2.z+a2.w) + (b2v.x+b2v.y)+(b2v.z+b2v.w);
            #pragma unroll
            for (int o = 16; o; o >>= 1) {
                s0 += __shfl_xor_sync(~0u, s0, o);
                s1 += __shfl_xor_sync(~0u, s1, o);
                s2 += __shfl_xor_sync(~0u, s2, o);
            }
            if ((tid & 31) == 0) {
                red[0][tid >> 5] = s0; red[1][tid >> 5] = s1; red[2][tid >> 5] = s2;
            }
        }
        __syncthreads();

        if (valid && tid == 0) {
            const float q0 = red[0][0] + red[0][1] + red[0][2] + red[0][3];
            const float q1 = red[1][0] + red[1][1] + red[1][2] + red[1][3];
            const float q2 = red[2][0] + red[2][1] + red[2][2] + red[2][3];
            const int off = item * 3;
            g_part[off + 0] = q0; g_part[off + 1] = q1; g_part[off + 2] = q2;
            __threadfence();                     // partials before arrival
            const int old = atomicAdd(&g_cnt[b], 1);
            tgt = old - (old % NSL) + NSL;       // end of THIS epoch
        }

        // ---- finish PENDING contrast item (its image completed ~1 round ago)
        if (p_item >= 0) {
            if (tid == 0) {
                volatile int* c = &g_cnt[p_b];
                while (*c < p_tgt) __nanosleep(32);
            }
            __syncthreads();                     // spin result visible to CTA
            if (tid < 96) {
                const int c    = tid >> 5;
                const int lane = tid & 31;
                float s = 0.f;
                const int base = p_b * NSL;
                if (lane < NSL)      s  = __ldcg(&g_part[(base + lane) * 3 + c]);
                if (lane + 32 < NSL) s += __ldcg(&g_part[(base + lane + 32) * 3 + c]);
                #pragma unroll
                for (int o = 16; o; o >>= 1)
                    s += __shfl_xor_sync(~0u, s, o);
                if (lane == 0)
                    sm_mean[c] = s * (1.0f / (float)HW_);
            }
            __syncthreads();

            const float m0 = sm_mean[0], m1 = sm_mean[1], m2 = sm_mean[2];
            const float gm = GW0 * m0 + GW1 * m1 + GW2 * m2;
            const float mm0 = (p_gray ? gm : m0) * p_br;
            const float mm1 = (p_gray ? gm : m1) * p_br;
            const float mm2 = (p_gray ? gm : m2) * p_br;
            const float sc   = p_br * p_cf;
            const float omcf = 1.0f - p_cf;
            const float of0 = mm0 * omcf, of1 = mm1 * omcf, of2 = mm2 * omcf;

            if (p_flip) { REV(pa0) REV(pa1) REV(pa2) REV(pb0) REV(pb1) REV(pb2) }
            if (p_gray) { GRAYIFY(pa0, pa1, pa2) GRAYIFY(pb0, pb1, pb2) }
            XFORM(pa0, sc, of0) XFORM(pa1, sc, of1) XFORM(pa2, sc, of2)
            XFORM(pb0, sc, of0) XFORM(pb1, sc, of1) XFORM(pb2, sc, of2)

            float4* __restrict__ o4 = oput + (size_t)p_b * 3 * HW4;
            __stcs(&o4[0 * HW4 + p_p0], pa0);
            __stcs(&o4[1 * HW4 + p_p0], pa1);
            __stcs(&o4[2 * HW4 + p_p0], pa2);
            __stcs(&o4[0 * HW4 + p_p0 + 128], pb0);
            __stcs(&o4[1 * HW4 + p_p0 + 128], pb1);
            __stcs(&o4[2 * HW4 + p_p0 + 128], pb2);
            p_item = -1;
        }

        // ---- current item: finish non-contrast now, stash contrast --------
        if (valid) {
            if (!ctr) {
                if (flip) { REV(a0) REV(a1) REV(a2) REV(b0v) REV(b1v) REV(b2v) }
                if (gray) { GRAYIFY(a0, a1, a2) GRAYIFY(b0v, b1v, b2v) }
                XFORM(a0, br, 0.f) XFORM(a1, br, 0.f) XFORM(a2, br, 0.f)
                XFORM(b0v, br, 0.f) XFORM(b1v, br, 0.f) XFORM(b2v, br, 0.f)
                float4* __restrict__ o4 = oput + (size_t)b * 3 * HW4;
                __stcs(&o4[0 * HW4 + p0], a0);
                __stcs(&o4[1 * HW4 + p0], a1);
                __stcs(&o4[2 * HW4 + p0], a2);
                __stcs(&o4[0 * HW4 + p0 + 128], b0v);
                __stcs(&o4[1 * HW4 + p0 + 128], b1v);
                __stcs(&o4[2 * HW4 + p0 + 128], b2v);
            } else {
                p_item = item; p_b = b; p_p0 = p0; p_tgt = tgt;
                p_flip = flip; p_gray = gray; p_br = br; p_cf = cf;
                pa0 = a0; pa1 = a1; pa2 = a2; pb0 = b0v; pb1 = b1v; pb2 = b2v;
            }
        }
        __syncthreads();                         // protect red/sm_mean reuse
    }

    #undef REV
    #undef GRAYIFY
    #undef XFORM
}

extern "C" void kernel_launch(void* const* d_in, const int* in_sizes, int n_in,
                              void* d_out, int out_size) {
    const float* x   = (const float*)d_in[0];
    const float* br  = (const float*)d_in[1];
    const float* cfv = (const float*)d_in[2];
    const int*   fm  = (const int*)d_in[3];
    const int*   gm  = (const int*)d_in[4];
    const int*   ca  = (const int*)d_in[5];
    float* out = (float*)d_out;

    fused_aug_kernel<<<NCTA, NT>>>(x, br, cfv, fm, gm, ca, out);
}

// round 17
// speedup vs baseline: 1.1106x; 1.1106x over previous
#include <cuda_runtime.h>

#define B_   256
#define C_   3
#define H_   224
#define W_   224
#define HW_  (H_ * W_)          // 50176
#define HW4  (HW_ / 4)          // 12544 float4 per plane
#define NSL  49                 // slices per image (CTAs in x)

#define GW0 0.2989f
#define GW1 0.587f
#define GW2 0.114f

// Deterministic scratch: per-(image,slice) channel partial sums.
__device__ float g_part[B_ * NSL * 3];

// ---------------------------------------------------------------------------
// Kernel A: read input ONCE; per-slice channel sums. Non-contrast images are
// finished here (clip(aug(x)*br)). IMAGE ORDER IS PERMUTED so contrast images
// are processed in the LAST waves: their __ldcg lines are the freshest L2
// content when A drains, maximizing C's hit rate on the re-read.
// ---------------------------------------------------------------------------
__global__ __launch_bounds__(256) void sum_and_easy_kernel(
    const float* __restrict__ x,
    const float* __restrict__ brightness,
    const int*   __restrict__ flip_mask,
    const int*   __restrict__ gray_mask,
    const int*   __restrict__ contrast_apply,
    float*       __restrict__ out)
{
    const int tid = threadIdx.x;
    const int sl  = blockIdx.x;
    const int p   = sl * 256 + tid;                      // < HW4 (49*256)

    // ---- deterministic permutation: non-contrast images first -------------
    // Thread tid owns image tid (256 threads == 256 images). Rank images so
    // all non-contrast (in index order) precede all contrast (in index
    // order); the thread whose rank == blockIdx.y publishes its image id.
    __shared__ int wcnt[8];
    __shared__ int sb;
    {
        const int  flag = contrast_apply[tid] != 0;      // L1-hot broadcast
        const unsigned bal  = __ballot_sync(~0u, flag);
        const int  wid  = tid >> 5;
        const int  lane = tid & 31;
        if (lane == 0) wcnt[wid] = __popc(bal);
        __syncthreads();
        int ctr_prefix = 0, total_ctr = 0;
        #pragma unroll
        for (int i = 0; i < 8; i++) {
            const int c = wcnt[i];
            if (i < wid) ctr_prefix += c;
            total_ctr += c;
        }
        const int ctr_before = ctr_prefix + __popc(bal & ((1u << lane) - 1));
        const int nc_total   = B_ - total_ctr;
        const int pos = flag ? (nc_total + ctr_before)   // contrast: tail
                             : (tid - ctr_before);       // non-contrast: head
        if (pos == (int)blockIdx.y) sb = tid;
        __syncthreads();
    }
    const int b = sb;

    const float br   = brightness[b];
    const bool  flip = flip_mask[b] != 0;
    const bool  gray = gray_mask[b] != 0;
    const bool  ctr  = contrast_apply[b] != 0;

    // flip-aware source (sum is flip-invariant)
    const int pix = p * 4;
    const int h   = pix / W_;
    const int w   = pix - h * W_;
    const int sp4 = flip ? ((h * W_ + (W_ - 4 - w)) >> 2) : p;

    const float4* __restrict__ in4 =
        reinterpret_cast<const float4*>(x) + (size_t)b * 3 * HW4;

    float4 v0, v1, v2;
    if (ctr) {      // keep resident in L2 for kernel C (freshest: last waves)
        v0 = __ldcg(&in4[0 * HW4 + sp4]);
        v1 = __ldcg(&in4[1 * HW4 + sp4]);
        v2 = __ldcg(&in4[2 * HW4 + sp4]);
    } else {        // dead after this kernel
        v0 = __ldcs(&in4[0 * HW4 + sp4]);
        v1 = __ldcs(&in4[1 * HW4 + sp4]);
        v2 = __ldcs(&in4[2 * HW4 + sp4]);
    }

    // per-channel partial sums of ORIGINAL x
    float s0 = (v0.x + v0.y) + (v0.z + v0.w);
    float s1 = (v1.x + v1.y) + (v1.z + v1.w);
    float s2 = (v2.x + v2.y) + (v2.z + v2.w);
    #pragma unroll
    for (int o = 16; o; o >>= 1) {
        s0 += __shfl_xor_sync(~0u, s0, o);
        s1 += __shfl_xor_sync(~0u, s1, o);
        s2 += __shfl_xor_sync(~0u, s2, o);
    }
    __shared__ float red[3][8];
    if ((tid & 31) == 0) {
        red[0][tid >> 5] = s0; red[1][tid >> 5] = s1; red[2][tid >> 5] = s2;
    }
    __syncthreads();
    if (tid == 0) {
        float a0 = 0.f, a1 = 0.f, a2 = 0.f;
        #pragma unroll
        for (int q = 0; q < 8; q++) { a0 += red[0][q]; a1 += red[1][q]; a2 += red[2][q]; }
        const int off = (b * NSL + sl) * 3;
        g_part[off + 0] = a0; g_part[off + 1] = a1; g_part[off + 2] = a2;
    }

    if (ctr) return;                                     // finished in kernel C

    // ---- no-contrast path: out = clip(aug(x)*br) ----
    if (flip) {
        float t;
        t = v0.x; v0.x = v0.w; v0.w = t;  t = v0.y; v0.y = v0.z; v0.z = t;
        t = v1.x; v1.x = v1.w; v1.w = t;  t = v1.y; v1.y = v1.z; v1.z = t;
        t = v2.x; v2.x = v2.w; v2.w = t;  t = v2.y; v2.y = v2.z; v2.z = t;
    }
    if (gray) {
        float4 g;
        g.x = GW0 * v0.x + GW1 * v1.x + GW2 * v2.x;
        g.y = GW0 * v0.y + GW1 * v1.y + GW2 * v2.y;
        g.z = GW0 * v0.z + GW1 * v1.z + GW2 * v2.z;
        g.w = GW0 * v0.w + GW1 * v1.w + GW2 * v2.w;
        v0 = g; v1 = g; v2 = g;
    }
    #define XFB(v)                                                           \
        v.x = fminf(fmaxf(v.x * br, -2.5f), 2.5f);                           \
        v.y = fminf(fmaxf(v.y * br, -2.5f), 2.5f);                           \
        v.z = fminf(fmaxf(v.z * br, -2.5f), 2.5f);                           \
        v.w = fminf(fmaxf(v.w * br, -2.5f), 2.5f);
    XFB(v0) XFB(v1) XFB(v2)
    #undef XFB

    float4* __restrict__ out4 =
        reinterpret_cast<float4*>(out) + (size_t)b * 3 * HW4;
    __stcs(&out4[0 * HW4 + p], v0);
    __stcs(&out4[1 * HW4 + p], v1);
    __stcs(&out4[2 * HW4 + p], v2);
}

// ---------------------------------------------------------------------------
// Kernel C: contrast images only. 128 threads per CTA, 2 pixels per thread
// (6 independent loads -> MLP 6). Non-contrast CTAs exit immediately.
// Identical to the proven R13 version.
// ---------------------------------------------------------------------------
__global__ __launch_bounds__(128) void contrast_kernel(
    const float* __restrict__ x,
    const float* __restrict__ brightness,
    const float* __restrict__ contrast_factor,
    const int*   __restrict__ flip_mask,
    const int*   __restrict__ gray_mask,
    const int*   __restrict__ contrast_apply,
    float*       __restrict__ out)
{
    const int b = blockIdx.y;
    if (contrast_apply[b] == 0) return;

    const int tid = threadIdx.x;
    const int p0  = blockIdx.x * 256 + tid;              // pixel A
    const int p1  = p0 + 128;                            // pixel B

    const float br   = brightness[b];
    const bool  flip = flip_mask[b] != 0;
    const bool  gray = gray_mask[b] != 0;
    const float cf   = contrast_factor[b];

    // A's g_part writes must be visible before the reduction.
    cudaGridDependencySynchronize();

    const int pixA = p0 * 4, hA = pixA / W_, wA = pixA - hA * W_;
    const int pixB = p1 * 4, hB = pixB / W_, wB = pixB - hB * W_;
    const int spA  = flip ? ((hA * W_ + (W_ - 4 - wA)) >> 2) : p0;
    const int spB  = flip ? ((hB * W_ + (W_ - 4 - wB)) >> 2) : p1;

    const float4* __restrict__ in4 =
        reinterpret_cast<const float4*>(x) + (size_t)b * 3 * HW4;
    float4 a0 = __ldcs(&in4[0 * HW4 + spA]);
    float4 a1 = __ldcs(&in4[1 * HW4 + spA]);
    float4 a2 = __ldcs(&in4[2 * HW4 + spA]);
    float4 b0 = __ldcs(&in4[0 * HW4 + spB]);
    float4 b1 = __ldcs(&in4[1 * HW4 + spB]);
    float4 b2 = __ldcs(&in4[2 * HW4 + spB]);

    __shared__ float sm_mean[3];
    if (tid < 96) {
        const int c    = tid >> 5;
        const int lane = tid & 31;
        float s = 0.f;
        if (lane < NSL)      s  = g_part[(b * NSL + lane) * 3 + c];
        if (lane + 32 < NSL) s += g_part[(b * NSL + lane + 32) * 3 + c];
        #pragma unroll
        for (int o = 16; o; o >>= 1)
            s += __shfl_xor_sync(~0u, s, o);
        if (lane == 0)
            sm_mean[c] = s * (1.0f / (float)HW_);
    }
    __syncthreads();

    const float m0 = sm_mean[0];
    const float m1 = sm_mean[1];
    const float m2 = sm_mean[2];
    const float gm = GW0 * m0 + GW1 * m1 + GW2 * m2;

    const float mm0 = (gray ? gm : m0) * br;
    const float mm1 = (gray ? gm : m1) * br;
    const float mm2 = (gray ? gm : m2) * br;

    const float scale = br * cf;
    const float omcf  = 1.0f - cf;
    const float off0 = mm0 * omcf;
    const float off1 = mm1 * omcf;
    const float off2 = mm2 * omcf;

    #define REV(v) { float t;                                                \
        t = v.x; v.x = v.w; v.w = t;  t = v.y; v.y = v.z; v.z = t; }
    if (flip) {
        REV(a0) REV(a1) REV(a2) REV(b0) REV(b1) REV(b2)
    }
    #undef REV

    if (gray) {
        float4 g;
        g.x = GW0*a0.x + GW1*a1.x + GW2*a2.x;
        g.y = GW0*a0.y + GW1*a1.y + GW2*a2.y;
        g.z = GW0*a0.z + GW1*a1.z + GW2*a2.z;
        g.w = GW0*a0.w + GW1*a1.w + GW2*a2.w;
        a0 = g; a1 = g; a2 = g;
        g.x = GW0*b0.x + GW1*b1.x + GW2*b2.x;
        g.y = GW0*b0.y + GW1*b1.y + GW2*b2.y;
        g.z = GW0*b0.z + GW1*b1.z + GW2*b2.z;
        g.w = GW0*b0.w + GW1*b1.w + GW2*b2.w;
        b0 = g; b1 = g; b2 = g;
    }

    #define XFORM(v, off)                                                    \
        v.x = fminf(fmaxf(fmaf(v.x, scale, off), -2.5f), 2.5f);             \
        v.y = fminf(fmaxf(fmaf(v.y, scale, off), -2.5f), 2.5f);             \
        v.z = fminf(fmaxf(fmaf(v.z, scale, off), -2.5f), 2.5f);             \
        v.w = fminf(fmaxf(fmaf(v.w, scale, off), -2.5f), 2.5f);
    XFORM(a0, off0) XFORM(a1, off1) XFORM(a2, off2)
    XFORM(b0, off0) XFORM(b1, off1) XFORM(b2, off2)
    #undef XFORM

    float4* __restrict__ out4 =
        reinterpret_cast<float4*>(out) + (size_t)b * 3 * HW4;
    __stcs(&out4[0 * HW4 + p0], a0);
    __stcs(&out4[1 * HW4 + p0], a1);
    __stcs(&out4[2 * HW4 + p0], a2);
    __stcs(&out4[0 * HW4 + p1], b0);
    __stcs(&out4[1 * HW4 + p1], b1);
    __stcs(&out4[2 * HW4 + p1], b2);
}

extern "C" void kernel_launch(void* const* d_in, const int* in_sizes, int n_in,
                              void* d_out, int out_size) {
    const float* x   = (const float*)d_in[0];
    const float* br  = (const float*)d_in[1];
    const float* cfv = (const float*)d_in[2];
    const int*   fm  = (const int*)d_in[3];
    const int*   gm  = (const int*)d_in[4];
    const int*   ca  = (const int*)d_in[5];
    float* out = (float*)d_out;

    dim3 grid(NSL, B_);                                  // (49, 256)
    sum_and_easy_kernel<<<grid, 256>>>(x, br, fm, gm, ca, out);

    // PDL launch: C's setup overlaps A; C's work starts when A drains
    // (implicit completion — A never calls the explicit trigger).
    cudaLaunchConfig_t cfg = {};
    cfg.gridDim  = grid;
    cfg.blockDim = dim3(128, 1, 1);
    cfg.stream   = 0;
    cudaLaunchAttribute attr[1];
    attr[0].id = cudaLaunchAttributeProgrammaticStreamSerialization;
    attr[0].val.programmaticStreamSerializationAllowed = 1;
    cfg.attrs    = attr;
    cfg.numAttrs = 1;
    cudaLaunchKernelEx(&cfg, contrast_kernel, x, br, cfv, fm, gm, ca, out);
}